// round 1
// baseline (speedup 1.0000x reference)
#include <cuda_runtime.h>
#include <cuda_bf16.h>
#include <math.h>

// Problem constants
constexpr int B_ = 2, T_ = 2048, C_ = 2048, H_ = 16, HD_ = 128;
constexpr int M_ = B_ * T_;          // 4096
constexpr int N_QKV = 3 * C_;        // 6144

// Scratch (allocation-free: __device__ globals)
__device__ float g_Q[(size_t)B_ * H_ * T_ * HD_];   // [B,H,T,HD]
__device__ float g_K[(size_t)B_ * H_ * T_ * HD_];
__device__ float g_V[(size_t)B_ * H_ * T_ * HD_];
__device__ float g_Y[(size_t)M_ * C_];              // attention out, [B*T, C]

// ---------------------------------------------------------------------------
// SGEMM 128x128x16, 256 threads, 8x8 microtile.
// Variant 1: QKV projection. A = x [4096,2048], B = W_qkv [2048,6144].
// Epilogue scatters into g_Q/g_K/g_V with [B,H,T,HD] layout.
// ---------------------------------------------------------------------------
__global__ void __launch_bounds__(256)
sgemm_qkv(const float* __restrict__ A, const float* __restrict__ Bm) {
    __shared__ float As[16 * 132];   // [k][m], padded stride 132
    __shared__ float Bs[16 * 128];   // [k][n]

    const int tid = threadIdx.x;
    const int bm = blockIdx.y, bn = blockIdx.x;
    const int tx = tid & 15, ty = tid >> 4;

    float acc[8][8];
    #pragma unroll
    for (int i = 0; i < 8; i++)
        #pragma unroll
        for (int j = 0; j < 8; j++) acc[i][j] = 0.f;

    for (int k0 = 0; k0 < C_; k0 += 16) {
        // Load A tile 128x16 (transposed into As)
        #pragma unroll
        for (int it = 0; it < 2; it++) {
            int e   = it * 256 + tid;
            int row = e >> 2, c4 = e & 3;
            float4 a = *(const float4*)(A + (size_t)(bm * 128 + row) * C_ + k0 + c4 * 4);
            As[(c4 * 4 + 0) * 132 + row] = a.x;
            As[(c4 * 4 + 1) * 132 + row] = a.y;
            As[(c4 * 4 + 2) * 132 + row] = a.z;
            As[(c4 * 4 + 3) * 132 + row] = a.w;
        }
        // Load B tile 16x128
        #pragma unroll
        for (int it = 0; it < 2; it++) {
            int e   = it * 256 + tid;
            int row = e >> 5, c4 = e & 31;
            float4 b = *(const float4*)(Bm + (size_t)(k0 + row) * N_QKV + bn * 128 + c4 * 4);
            *(float4*)(Bs + row * 128 + c4 * 4) = b;
        }
        __syncthreads();

        #pragma unroll
        for (int k = 0; k < 16; k++) {
            float4 a0 = *(const float4*)(As + k * 132 + ty * 8);
            float4 a1 = *(const float4*)(As + k * 132 + ty * 8 + 4);
            float4 b0 = *(const float4*)(Bs + k * 128 + tx * 8);
            float4 b1 = *(const float4*)(Bs + k * 128 + tx * 8 + 4);
            float ra[8] = {a0.x, a0.y, a0.z, a0.w, a1.x, a1.y, a1.z, a1.w};
            float rb[8] = {b0.x, b0.y, b0.z, b0.w, b1.x, b1.y, b1.z, b1.w};
            #pragma unroll
            for (int i = 0; i < 8; i++)
                #pragma unroll
                for (int j = 0; j < 8; j++)
                    acc[i][j] = fmaf(ra[i], rb[j], acc[i][j]);
        }
        __syncthreads();
    }

    // Epilogue: n-tile maps to a single (s, h)
    const int b  = bm >> 4;                  // bm*128 / 2048
    const int t0 = (bm & 15) * 128;
    const int n0 = bn * 128;
    const int s  = n0 >> 11;                 // / 2048
    const int h  = (n0 & 2047) >> 7;         // / 128
    float* dst  = (s == 0) ? g_Q : (s == 1) ? g_K : g_V;
    float* base = dst + (size_t)(b * H_ + h) * T_ * HD_;

    #pragma unroll
    for (int i = 0; i < 8; i++) {
        int t = t0 + ty * 8 + i;
        float* rowp = base + (size_t)t * HD_ + tx * 8;
        *(float4*)(rowp + 0) = make_float4(acc[i][0], acc[i][1], acc[i][2], acc[i][3]);
        *(float4*)(rowp + 4) = make_float4(acc[i][4], acc[i][5], acc[i][6], acc[i][7]);
    }
}

// ---------------------------------------------------------------------------
// Variant 2: output projection. A = g_Y [4096,2048], B = W_proj [2048,2048].
// ---------------------------------------------------------------------------
__global__ void __launch_bounds__(256)
sgemm_proj(const float* __restrict__ Bm, const float* __restrict__ bias,
           float* __restrict__ out) {
    __shared__ float As[16 * 132];
    __shared__ float Bs[16 * 128];

    const int tid = threadIdx.x;
    const int bm = blockIdx.y, bn = blockIdx.x;
    const int tx = tid & 15, ty = tid >> 4;

    float acc[8][8];
    #pragma unroll
    for (int i = 0; i < 8; i++)
        #pragma unroll
        for (int j = 0; j < 8; j++) acc[i][j] = 0.f;

    for (int k0 = 0; k0 < C_; k0 += 16) {
        #pragma unroll
        for (int it = 0; it < 2; it++) {
            int e   = it * 256 + tid;
            int row = e >> 2, c4 = e & 3;
            float4 a = *(const float4*)(g_Y + (size_t)(bm * 128 + row) * C_ + k0 + c4 * 4);
            As[(c4 * 4 + 0) * 132 + row] = a.x;
            As[(c4 * 4 + 1) * 132 + row] = a.y;
            As[(c4 * 4 + 2) * 132 + row] = a.z;
            As[(c4 * 4 + 3) * 132 + row] = a.w;
        }
        #pragma unroll
        for (int it = 0; it < 2; it++) {
            int e   = it * 256 + tid;
            int row = e >> 5, c4 = e & 31;
            float4 b = *(const float4*)(Bm + (size_t)(k0 + row) * C_ + bn * 128 + c4 * 4);
            *(float4*)(Bs + row * 128 + c4 * 4) = b;
        }
        __syncthreads();

        #pragma unroll
        for (int k = 0; k < 16; k++) {
            float4 a0 = *(const float4*)(As + k * 132 + ty * 8);
            float4 a1 = *(const float4*)(As + k * 132 + ty * 8 + 4);
            float4 b0 = *(const float4*)(Bs + k * 128 + tx * 8);
            float4 b1 = *(const float4*)(Bs + k * 128 + tx * 8 + 4);
            float ra[8] = {a0.x, a0.y, a0.z, a0.w, a1.x, a1.y, a1.z, a1.w};
            float rb[8] = {b0.x, b0.y, b0.z, b0.w, b1.x, b1.y, b1.z, b1.w};
            #pragma unroll
            for (int i = 0; i < 8; i++)
                #pragma unroll
                for (int j = 0; j < 8; j++)
                    acc[i][j] = fmaf(ra[i], rb[j], acc[i][j]);
        }
        __syncthreads();
    }

    const int n = bn * 128 + tx * 8;
    float bj[8];
    #pragma unroll
    for (int j = 0; j < 8; j++) bj[j] = bias[n + j];

    #pragma unroll
    for (int i = 0; i < 8; i++) {
        int m = bm * 128 + ty * 8 + i;
        float* rowp = out + (size_t)m * C_ + n;
        *(float4*)(rowp + 0) = make_float4(acc[i][0] + bj[0], acc[i][1] + bj[1],
                                           acc[i][2] + bj[2], acc[i][3] + bj[3]);
        *(float4*)(rowp + 4) = make_float4(acc[i][4] + bj[4], acc[i][5] + bj[5],
                                           acc[i][6] + bj[6], acc[i][7] + bj[7]);
    }
}

// ---------------------------------------------------------------------------
// Flash-attention, fp32, causal. Br=Bc=64, HD=128, 256 threads.
// Thread t: row r = t>>2 (of 64); S-step covers k cols [(t&3)*16, +16),
// O-step covers d cols [(t&3)*32, +32). m/l/alpha live in registers
// (replicated across the 4 lanes of a row group via shfl).
// ---------------------------------------------------------------------------
constexpr int QS_STRIDE = 129;
constexpr int SS_STRIDE = 65;
constexpr int ATTN_SMEM_FLOATS = 64 * QS_STRIDE * 2 + 64 * HD_ + 64 * SS_STRIDE;
constexpr int ATTN_SMEM_BYTES  = ATTN_SMEM_FLOATS * 4;   // 115,456 B

__global__ void __launch_bounds__(256)
attn_kernel() {
    extern __shared__ float sm[];
    float* Qs = sm;                        // [64][129]
    float* Ks = Qs + 64 * QS_STRIDE;       // [64][129]
    float* Vs = Ks + 64 * QS_STRIDE;       // [64][128]
    float* Ss = Vs + 64 * HD_;             // [64][65]

    const int tid = threadIdx.x;
    const int qi = blockIdx.x, h = blockIdx.y, b = blockIdx.z;
    const int q0 = qi * 64;

    const size_t bh = (size_t)(b * H_ + h) * T_ * HD_;
    const float* Qg = g_Q + bh;
    const float* Kg = g_K + bh;
    const float* Vg = g_V + bh;

    // Load Q tile, pre-scaled by 1/sqrt(HD)
    constexpr float SCALE = 0.08838834764831845f;  // 128^-0.5
    for (int e = tid; e < 64 * HD_; e += 256) {
        int r = e >> 7, c = e & 127;
        Qs[r * QS_STRIDE + c] = Qg[(size_t)(q0 + r) * HD_ + c] * SCALE;
    }

    const int qr = tid >> 2;
    const int kb = (tid & 3) * 16;
    const int c0 = (tid & 3) * 32;

    float m = -1e30f, l = 0.f;
    float acc[32];
    #pragma unroll
    for (int j = 0; j < 32; j++) acc[j] = 0.f;

    __syncthreads();

    for (int kt = 0; kt <= qi; kt++) {
        const int k0 = kt * 64;
        // Load K, V tiles
        for (int e = tid; e < 64 * HD_; e += 256) {
            int r = e >> 7, c = e & 127;
            Ks[r * QS_STRIDE + c] = Kg[(size_t)(k0 + r) * HD_ + c];
            Vs[r * HD_ + c]       = Vg[(size_t)(k0 + r) * HD_ + c];
        }
        __syncthreads();

        // S = (Q/sqrt(d)) K^T  (16 entries of row qr per thread)
        float s[16];
        #pragma unroll
        for (int j = 0; j < 16; j++) s[j] = 0.f;
        for (int d = 0; d < HD_; d++) {
            float qv = Qs[qr * QS_STRIDE + d];
            #pragma unroll
            for (int j = 0; j < 16; j++)
                s[j] = fmaf(qv, Ks[(kb + j) * QS_STRIDE + d], s[j]);
        }

        // Causal mask (only on the diagonal tile)
        if (kt == qi) {
            #pragma unroll
            for (int j = 0; j < 16; j++)
                if (k0 + kb + j > q0 + qr) s[j] = -1e30f;
        }

        // Online softmax: tile max across 4 lanes of this row group
        float tmax = s[0];
        #pragma unroll
        for (int j = 1; j < 16; j++) tmax = fmaxf(tmax, s[j]);
        tmax = fmaxf(tmax, __shfl_xor_sync(0xffffffffu, tmax, 1));
        tmax = fmaxf(tmax, __shfl_xor_sync(0xffffffffu, tmax, 2));

        float mnew  = fmaxf(m, tmax);
        float alpha = __expf(m - mnew);

        float psum = 0.f;
        #pragma unroll
        for (int j = 0; j < 16; j++) {
            float p = __expf(s[j] - mnew);
            Ss[qr * SS_STRIDE + kb + j] = p;
            psum += p;
        }
        psum += __shfl_xor_sync(0xffffffffu, psum, 1);
        psum += __shfl_xor_sync(0xffffffffu, psum, 2);
        l = l * alpha + psum;
        m = mnew;

        __syncthreads();   // Ss complete before PV reads

        // Rescale accumulators, then O += P @ V (32 cols of row qr per thread)
        #pragma unroll
        for (int j = 0; j < 32; j++) acc[j] *= alpha;

        for (int k = 0; k < 64; k++) {
            float p = Ss[qr * SS_STRIDE + k];
            const float4* vrow = (const float4*)(Vs + k * HD_ + c0);
            #pragma unroll
            for (int j4 = 0; j4 < 8; j4++) {
                float4 v = vrow[j4];
                acc[j4 * 4 + 0] = fmaf(p, v.x, acc[j4 * 4 + 0]);
                acc[j4 * 4 + 1] = fmaf(p, v.y, acc[j4 * 4 + 1]);
                acc[j4 * 4 + 2] = fmaf(p, v.z, acc[j4 * 4 + 2]);
                acc[j4 * 4 + 3] = fmaf(p, v.w, acc[j4 * 4 + 3]);
            }
        }
        __syncthreads();   // before next tile overwrites Ks/Vs/Ss
    }

    // Normalize and write: y[b*T + t][h*HD + d]
    float inv = 1.f / l;
    float* yrow = g_Y + ((size_t)(b * T_ + q0 + qr)) * C_ + h * HD_ + c0;
    #pragma unroll
    for (int j4 = 0; j4 < 8; j4++) {
        *(float4*)(yrow + j4 * 4) = make_float4(acc[j4 * 4 + 0] * inv,
                                                acc[j4 * 4 + 1] * inv,
                                                acc[j4 * 4 + 2] * inv,
                                                acc[j4 * 4 + 3] * inv);
    }
}

// ---------------------------------------------------------------------------
// Launch: qkv GEMM -> attention -> proj GEMM (default stream, graph-capturable)
// Inputs (metadata order): x, mask, W_qkv, W_proj, b_proj
// ---------------------------------------------------------------------------
extern "C" void kernel_launch(void* const* d_in, const int* in_sizes, int n_in,
                              void* d_out, int out_size) {
    const float* x     = (const float*)d_in[0];
    const float* Wqkv  = (const float*)d_in[2];
    const float* Wproj = (const float*)d_in[3];
    const float* bproj = (const float*)d_in[4];
    float* out = (float*)d_out;

    static bool attr_set = false;
    if (!attr_set) {
        cudaFuncSetAttribute(attn_kernel,
                             cudaFuncAttributeMaxDynamicSharedMemorySize,
                             ATTN_SMEM_BYTES);
        attr_set = true;
    }

    sgemm_qkv<<<dim3(N_QKV / 128, M_ / 128), 256>>>(x, Wqkv);
    attn_kernel<<<dim3(T_ / 64, H_, B_), 256, ATTN_SMEM_BYTES>>>();
    sgemm_proj<<<dim3(C_ / 128, M_ / 128), 256>>>(Wproj, bproj, out);
}